// round 8
// baseline (speedup 1.0000x reference)
#include <cuda_runtime.h>
#include <cstdint>
#include <cstddef>
#include <math.h>

// ---------------------------------------------------------------------------
// LSTM  I=256 H=512 O=10 B=64 T=2048  (fp32, f32x2 packed-FMA pipe)
// R7: R6 compute kept; chip-barrier fixed (single-warp relaxed poll + one
//     acquire fence -- R6's 16K-thread acquire poll storm serialized 4 hot
//     L2 lines and cost ~+4.5us/step). xg prefetch hoisted above barrier.
// ---------------------------------------------------------------------------

#define TSZ  2048
#define NCTA 128

typedef unsigned long long ull;

// scratch (__device__ globals are the sanctioned scratch mechanism)
__device__ float    g_xg[268435456];     // 1 GiB: [T][4H][B]  (2048*2048*64)
__device__ float    g_h[2 * 512 * 64];   // double-buffered h: [H][B]
__device__ float    g_bias[2048];        // b_ih + b_hh
__device__ unsigned g_flags[NCTA];       // per-CTA step flags (chip barrier)

// ---- packed f32x2 helpers (Blackwell dual-fp32 pipe) ----------------------
__device__ __forceinline__ ull pk2(float a, float b) {
    ull r; asm("mov.b64 %0,{%1,%2};" : "=l"(r) : "f"(a), "f"(b)); return r;
}
__device__ __forceinline__ ull splat2(float a) {
    ull r; asm("mov.b64 %0,{%1,%1};" : "=l"(r) : "f"(a)); return r;
}
__device__ __forceinline__ void upk2(ull v, float& a, float& b) {
    asm("mov.b64 {%0,%1},%2;" : "=f"(a), "=f"(b) : "l"(v));
}
__device__ __forceinline__ ull fma2(ull a, ull b, ull c) {
    ull d; asm("fma.rn.f32x2 %0,%1,%2,%3;" : "=l"(d) : "l"(a), "l"(b), "l"(c));
    return d;
}

// ---- smem / mbarrier / bulk-copy helpers ----------------------------------
__device__ __forceinline__ uint32_t s2u(const void* p) {
    uint32_t a;
    asm("{ .reg .u64 t; cvta.to.shared.u64 t, %1; cvt.u32.u64 %0, t; }"
        : "=r"(a) : "l"(p));
    return a;
}
__device__ __forceinline__ void mbar_init(uint32_t m, unsigned cnt) {
    asm volatile("mbarrier.init.shared.b64 [%0], %1;" :: "r"(m), "r"(cnt) : "memory");
}
__device__ __forceinline__ void mbar_expect_tx(uint32_t m, unsigned bytes) {
    asm volatile("mbarrier.arrive.expect_tx.shared.b64 _, [%0], %1;"
                 :: "r"(m), "r"(bytes) : "memory");
}
__device__ __forceinline__ void mbar_wait(uint32_t m, int phase) {
    asm volatile(
        "{\n\t.reg .pred P;\n\t"
        "LW_%=:\n\t"
        "mbarrier.try_wait.parity.acquire.cta.shared::cta.b64 P, [%0], %1, 0x989680;\n\t"
        "@P bra LD_%=;\n\t"
        "bra LW_%=;\n\t"
        "LD_%=:\n\t}"
        :: "r"(m), "r"(phase) : "memory");
}
__device__ __forceinline__ void bulk_g2s(uint32_t dst, const void* src,
                                         unsigned bytes, uint32_t mbar) {
    asm volatile(
        "cp.async.bulk.shared::cluster.global.mbarrier::complete_tx::bytes "
        "[%0], [%1], %2, [%3];"
        :: "r"(dst), "l"(src), "r"(bytes), "r"(mbar) : "memory");
}

// ---------------------------------------------------------------------------
__global__ void k_init(const float* __restrict__ bih, const float* __restrict__ bhh) {
    int tid = blockIdx.x * blockDim.x + threadIdx.x;
    int nt  = gridDim.x * blockDim.x;
    if (tid < 2048) g_bias[tid] = bih[tid] + bhh[tid];
    for (int i = tid; i < 2 * 512 * 64; i += nt) g_h[i] = 0.0f;
    if (tid < NCTA) g_flags[tid] = 0u;
}

// ---------------------------------------------------------------------------
// Phase 1: xg[t][row][b] = sum_i W_ih[row][i] * x[b][t][i] + bias[row]
// (unchanged -- passing since R5)
// ---------------------------------------------------------------------------
__global__ void __launch_bounds__(256) k_inproj(const float* __restrict__ x,
                                                const float* __restrict__ Wih) {
    __shared__ __align__(16) float As[16 * 132];
    __shared__ __align__(16) float Bs[16 * 66];

    const int tid = threadIdx.x;
    const int bx  = blockIdx.x;
    const int t   = blockIdx.y;
    const int tr  = tid >> 4, tc = tid & 15;
    const int r0  = tr * 8,  c0 = tc * 4;
    const int kkg = tid & 3;
    const int bb  = tid >> 2;

    ull acc[8][2];
#pragma unroll
    for (int i = 0; i < 8; i++) { acc[i][0] = 0ull; acc[i][1] = 0ull; }

    for (int k0 = 0; k0 < 256; k0 += 16) {
#pragma unroll
        for (int j = 0; j < 2; j++) {
            int rr = (tid >> 2) + j * 64;
            float4 av = *(const float4*)(Wih + (size_t)(bx * 128 + rr) * 256 + k0 + kkg * 4);
            As[(kkg * 4 + 0) * 132 + rr] = av.x;
            As[(kkg * 4 + 1) * 132 + rr] = av.y;
            As[(kkg * 4 + 2) * 132 + rr] = av.z;
            As[(kkg * 4 + 3) * 132 + rr] = av.w;
        }
        {
            float4 bv = *(const float4*)(x + ((size_t)bb * 2048 + t) * 256 + k0 + kkg * 4);
            Bs[(kkg * 4 + 0) * 66 + bb] = bv.x;
            Bs[(kkg * 4 + 1) * 66 + bb] = bv.y;
            Bs[(kkg * 4 + 2) * 66 + bb] = bv.z;
            Bs[(kkg * 4 + 3) * 66 + bb] = bv.w;
        }
        __syncthreads();
#pragma unroll
        for (int k = 0; k < 16; k++) {
            float4 a0 = *(const float4*)&As[k * 132 + r0];
            float4 a1 = *(const float4*)&As[k * 132 + r0 + 4];
            ull b0 = *(const ull*)&Bs[k * 66 + c0];
            ull b1 = *(const ull*)&Bs[k * 66 + c0 + 2];
            ull sp;
            sp = splat2(a0.x); acc[0][0] = fma2(sp, b0, acc[0][0]); acc[0][1] = fma2(sp, b1, acc[0][1]);
            sp = splat2(a0.y); acc[1][0] = fma2(sp, b0, acc[1][0]); acc[1][1] = fma2(sp, b1, acc[1][1]);
            sp = splat2(a0.z); acc[2][0] = fma2(sp, b0, acc[2][0]); acc[2][1] = fma2(sp, b1, acc[2][1]);
            sp = splat2(a0.w); acc[3][0] = fma2(sp, b0, acc[3][0]); acc[3][1] = fma2(sp, b1, acc[3][1]);
            sp = splat2(a1.x); acc[4][0] = fma2(sp, b0, acc[4][0]); acc[4][1] = fma2(sp, b1, acc[4][1]);
            sp = splat2(a1.y); acc[5][0] = fma2(sp, b0, acc[5][0]); acc[5][1] = fma2(sp, b1, acc[5][1]);
            sp = splat2(a1.z); acc[6][0] = fma2(sp, b0, acc[6][0]); acc[6][1] = fma2(sp, b1, acc[6][1]);
            sp = splat2(a1.w); acc[7][0] = fma2(sp, b0, acc[7][0]); acc[7][1] = fma2(sp, b1, acc[7][1]);
        }
        __syncthreads();
    }
#pragma unroll
    for (int i = 0; i < 8; i++) {
        int row = bx * 128 + r0 + i;
        float bias = g_bias[row];
        float p0, p1, p2, p3;
        upk2(acc[i][0], p0, p1);
        upk2(acc[i][1], p2, p3);
        *(float4*)(g_xg + ((size_t)t * 2048 + row) * 64 + c0) =
            make_float4(p0 + bias, p1 + bias, p2 + bias, p3 + bias);
    }
}

// ---------------------------------------------------------------------------
// Phase 2: persistent recurrence, 128 CTAs x 256 threads. (R6 compute kept)
// Chip barrier: tid0 release-store; warp 0 polls all 128 flags with RELAXED
// gpu-scope loads (4 flags/lane), then ONE fence.acq_rel.gpu.
// ---------------------------------------------------------------------------
__global__ void __launch_bounds__(256, 1) k_rec(const float* __restrict__ Whh) {
    extern __shared__ __align__(16) float sm[];
    ull*   Wt2 = (ull*)sm;            // 8192 ull  = 64 KB
    float* hsh = sm + 16384;          // 16384 fl  = 64 KB (2 x 32KB)
    float* gsh = sm + 32768;          // 1024 fl   =  4 KB
    __shared__ __align__(8) ull mbars[2];

    const int tid  = threadIdx.x;
    const int h0   = blockIdx.x * 4;
    const int wid  = tid >> 5, lane = tid & 31;
    const int rg   = lane >> 3, cg = lane & 7;
    const int wrow = (wid & 1) * 8 + rg * 2;       // even local row
    const int c    = (wid >> 1) * 16 + cg * 2;     // even col
    const int grow0 = (wrow & 3) * 512 + h0 + (wrow >> 2); // global gate row

    const uint32_t mb0 = s2u(&mbars[0]);
    const uint32_t mb1 = s2u(&mbars[1]);
    const uint32_t hsh_u = s2u(hsh);

    // load W slab pre-splatted: Wt2[k*16 + rloc] = {w,w}
#pragma unroll
    for (int j = 0; j < 8; j++) {
        int flat = tid + j * 256;
        int rl = flat >> 7, k4 = flat & 127;
        int grw = (rl & 3) * 512 + h0 + (rl >> 2);
        float4 w4 = *(const float4*)(Whh + (size_t)grw * 512 + k4 * 4);
        Wt2[(k4 * 4 + 0) * 16 + rl] = splat2(w4.x);
        Wt2[(k4 * 4 + 1) * 16 + rl] = splat2(w4.y);
        Wt2[(k4 * 4 + 2) * 16 + rl] = splat2(w4.z);
        Wt2[(k4 * 4 + 3) * 16 + rl] = splat2(w4.w);
    }
    if (tid == 0) { mbar_init(mb0, 1u); mbar_init(mb1, 1u); }
    float cstate = 0.0f;
    int ph0 = 0, ph1 = 0;
    __syncthreads();

    // prefetch xg for step 0
    float2 nx0 = __ldcs((const float2*)(g_xg + (size_t)grow0 * 64 + c));
    float2 nx1 = __ldcs((const float2*)(g_xg + (size_t)(grow0 + 512) * 64 + c));

    for (int s = 0; s < TSZ; s++) {
        const float* hin  = g_h + (s & 1) * 32768;
        float*       hout = g_h + ((s + 1) & 1) * 32768;

        ull acc0 = pk2(nx0.x, nx0.y);
        ull acc1 = pk2(nx1.x, nx1.y);

        // kick off first two 32KB h chunks
        if (tid == 0) {
            asm volatile("fence.proxy.async;" ::: "memory");
            mbar_expect_tx(mb0, 32768u);
            bulk_g2s(hsh_u, hin, 32768u, mb0);
            mbar_expect_tx(mb1, 32768u);
            bulk_g2s(hsh_u + 32768u, hin + 8192, 32768u, mb1);
        }

#pragma unroll
        for (int kc = 0; kc < 4; kc++) {
            const int buf = kc & 1;
            if (buf == 0) { mbar_wait(mb0, ph0); ph0 ^= 1; }
            else          { mbar_wait(mb1, ph1); ph1 ^= 1; }

            const ull*   wp = Wt2 + (kc * 128) * 16 + wrow;
            const float* hp = hsh + buf * 8192 + c;
#pragma unroll 8
            for (int kl = 0; kl < 128; kl++) {
                ulonglong2 w = *(const ulonglong2*)(wp + kl * 16);
                ull h2 = *(const ull*)(hp + kl * 64);
                acc0 = fma2(w.x, h2, acc0);
                acc1 = fma2(w.y, h2, acc1);
            }
            __syncthreads();
            if (kc < 2 && tid == 0) {
                const uint32_t m = buf ? mb1 : mb0;
                mbar_expect_tx(m, 32768u);
                bulk_g2s(hsh_u + buf * 32768u, hin + (kc + 2) * 8192, 32768u, m);
            }
        }

        // publish gate pre-activations
        *(ull*)(gsh + wrow * 64 + c)       = acc0;
        *(ull*)(gsh + (wrow + 1) * 64 + c) = acc1;
        __syncthreads();

        // cell update: one cell per thread
        {
            int u2 = tid >> 6, b = tid & 63;
            float ig = gsh[(u2 * 4 + 0) * 64 + b];
            float fg = gsh[(u2 * 4 + 1) * 64 + b];
            float gg = gsh[(u2 * 4 + 2) * 64 + b];
            float og = gsh[(u2 * 4 + 3) * 64 + b];
            ig = 1.0f / (1.0f + expf(-ig));
            fg = 1.0f / (1.0f + expf(-fg));
            gg = tanhf(gg);
            og = 1.0f / (1.0f + expf(-og));
            cstate = fg * cstate + ig * gg;
            hout[(h0 + u2) * 64 + b] = og * tanhf(cstate);
        }

        // prefetch next step's xg before the barrier (independent of h)
        if (s + 1 < TSZ) {
            nx0 = __ldcs((const float2*)(g_xg + ((size_t)(s + 1) * 2048 + grow0) * 64 + c));
            nx1 = __ldcs((const float2*)(g_xg + ((size_t)(s + 1) * 2048 + grow0 + 512) * 64 + c));
        }
        __syncthreads();                       // all hout STGs done (CTA view)

        // ---- chip barrier: 1 release store, 1 polling warp -----------------
        if (tid == 0) {
            asm volatile("st.global.release.gpu.u32 [%0], %1;"
                         :: "l"(&g_flags[blockIdx.x]), "r"(s + 1) : "memory");
        }
        if (tid < 32) {
            const unsigned target = (unsigned)(s + 1);
            const unsigned* f = g_flags + tid * 4;
            unsigned v0, v1, v2, v3;
            do {
                asm volatile("ld.global.relaxed.gpu.u32 %0,[%1];" : "=r"(v0) : "l"(f + 0));
                asm volatile("ld.global.relaxed.gpu.u32 %0,[%1];" : "=r"(v1) : "l"(f + 1));
                asm volatile("ld.global.relaxed.gpu.u32 %0,[%1];" : "=r"(v2) : "l"(f + 2));
                asm volatile("ld.global.relaxed.gpu.u32 %0,[%1];" : "=r"(v3) : "l"(f + 3));
            } while (v0 < target || v1 < target || v2 < target || v3 < target);
            asm volatile("fence.acq_rel.gpu;" ::: "memory");
        }
        __syncthreads();
    }
}

// ---------------------------------------------------------------------------
// FC head: warp-per-output, shfl reduction. (unchanged, 6.8us)
// ---------------------------------------------------------------------------
__global__ void __launch_bounds__(256) k_fc(const float* __restrict__ Wfc,
                                            const float* __restrict__ bfc,
                                            float* __restrict__ out) {
    int g    = blockIdx.x * 8 + (threadIdx.x >> 5);
    int lane = threadIdx.x & 31;
    int o = g >> 6, b = g & 63;
    float s = 0.0f;
#pragma unroll
    for (int j = 0; j < 16; j++) {
        int h = lane + j * 32;
        s += g_h[h * 64 + b] * Wfc[o * 512 + h];
    }
#pragma unroll
    for (int m = 16; m > 0; m >>= 1)
        s += __shfl_xor_sync(0xFFFFFFFFu, s, m);
    if (lane == 0) out[b * 10 + o] = s + bfc[o];
}

// ---------------------------------------------------------------------------
extern "C" void kernel_launch(void* const* d_in, const int* in_sizes, int n_in,
                              void* d_out, int out_size) {
    const float* x    = (const float*)d_in[0];
    const float* W_ih = (const float*)d_in[1];
    const float* W_hh = (const float*)d_in[2];
    const float* b_ih = (const float*)d_in[3];
    const float* b_hh = (const float*)d_in[4];
    const float* W_fc = (const float*)d_in[5];
    const float* b_fc = (const float*)d_in[6];
    float* out = (float*)d_out;

    const int SMEM_REC = (16384 + 16384 + 1024) * 4;   // 132 KB dynamic
    cudaFuncSetAttribute(k_rec, cudaFuncAttributeMaxDynamicSharedMemorySize, SMEM_REC);

    k_init<<<64, 256>>>(b_ih, b_hh);
    k_inproj<<<dim3(16, 2048), 256>>>(x, W_ih);
    k_rec<<<NCTA, 256, SMEM_REC>>>(W_hh);
    k_fc<<<80, 256>>>(W_fc, b_fc, out);
}

// round 9
// speedup vs baseline: 1.1934x; 1.1934x over previous
#include <cuda_runtime.h>
#include <cstdint>
#include <cstddef>
#include <math.h>

// ---------------------------------------------------------------------------
// LSTM  I=256 H=512 O=10 B=64 T=2048  (fp32, f32x2 packed-FMA pipe)
// R8: NO chip barrier. Per-CTA done-flags + per-chunk dataflow waits
//     (pipelined one chunk ahead). Data path reverted to proven R5 LDG/smem
//     double-buffer staging. Pre-splatted W in smem. Fast activations.
// ---------------------------------------------------------------------------

#define TSZ  2048
#define NCTA 128

typedef unsigned long long ull;

// scratch (__device__ globals are the sanctioned scratch mechanism)
__device__ float    g_xg[268435456];     // 1 GiB: [T][4H][B]  (2048*2048*64)
__device__ float    g_h[2 * 512 * 64];   // double-buffered h: [H][B]
__device__ float    g_bias[2048];        // b_ih + b_hh
__device__ unsigned g_flags[NCTA];       // per-CTA completed-step counters

// ---- packed f32x2 helpers (Blackwell dual-fp32 pipe) ----------------------
__device__ __forceinline__ ull pk2(float a, float b) {
    ull r; asm("mov.b64 %0,{%1,%2};" : "=l"(r) : "f"(a), "f"(b)); return r;
}
__device__ __forceinline__ ull splat2(float a) {
    ull r; asm("mov.b64 %0,{%1,%1};" : "=l"(r) : "f"(a)); return r;
}
__device__ __forceinline__ void upk2(ull v, float& a, float& b) {
    asm("mov.b64 {%0,%1},%2;" : "=f"(a), "=f"(b) : "l"(v));
}
__device__ __forceinline__ ull fma2(ull a, ull b, ull c) {
    ull d; asm("fma.rn.f32x2 %0,%1,%2,%3;" : "=l"(d) : "l"(a), "l"(b), "l"(c));
    return d;
}

// relaxed single-flag poll (steady state: 1 iteration)
__device__ __forceinline__ void poll_flag(const unsigned* f, unsigned target) {
    unsigned v;
    do {
        asm volatile("ld.relaxed.gpu.global.u32 %0,[%1];" : "=r"(v) : "l"(f));
    } while (v < target);
}
__device__ __forceinline__ void fence_acq() {
    asm volatile("fence.acq_rel.gpu;" ::: "memory");
}

// fast activations (rel err ~1e-6; budget 1e-3)
__device__ __forceinline__ float fsig(float x) {
    return __fdividef(1.0f, 1.0f + __expf(-x));
}
__device__ __forceinline__ float ftanh(float x) {
    return 1.0f - __fdividef(2.0f, __expf(2.0f * x) + 1.0f);
}

// ---------------------------------------------------------------------------
__global__ void k_init(const float* __restrict__ bih, const float* __restrict__ bhh) {
    int tid = blockIdx.x * blockDim.x + threadIdx.x;
    int nt  = gridDim.x * blockDim.x;
    if (tid < 2048) g_bias[tid] = bih[tid] + bhh[tid];
    for (int i = tid; i < 2 * 512 * 64; i += nt) g_h[i] = 0.0f;
    if (tid < NCTA) g_flags[tid] = 0u;
}

// ---------------------------------------------------------------------------
// Phase 1: xg[t][row][b] = sum_i W_ih[row][i] * x[b][t][i] + bias[row]
// (unchanged -- passing since R5)
// ---------------------------------------------------------------------------
__global__ void __launch_bounds__(256) k_inproj(const float* __restrict__ x,
                                                const float* __restrict__ Wih) {
    __shared__ __align__(16) float As[16 * 132];
    __shared__ __align__(16) float Bs[16 * 66];

    const int tid = threadIdx.x;
    const int bx  = blockIdx.x;
    const int t   = blockIdx.y;
    const int tr  = tid >> 4, tc = tid & 15;
    const int r0  = tr * 8,  c0 = tc * 4;
    const int kkg = tid & 3;
    const int bb  = tid >> 2;

    ull acc[8][2];
#pragma unroll
    for (int i = 0; i < 8; i++) { acc[i][0] = 0ull; acc[i][1] = 0ull; }

    for (int k0 = 0; k0 < 256; k0 += 16) {
#pragma unroll
        for (int j = 0; j < 2; j++) {
            int rr = (tid >> 2) + j * 64;
            float4 av = *(const float4*)(Wih + (size_t)(bx * 128 + rr) * 256 + k0 + kkg * 4);
            As[(kkg * 4 + 0) * 132 + rr] = av.x;
            As[(kkg * 4 + 1) * 132 + rr] = av.y;
            As[(kkg * 4 + 2) * 132 + rr] = av.z;
            As[(kkg * 4 + 3) * 132 + rr] = av.w;
        }
        {
            float4 bv = *(const float4*)(x + ((size_t)bb * 2048 + t) * 256 + k0 + kkg * 4);
            Bs[(kkg * 4 + 0) * 66 + bb] = bv.x;
            Bs[(kkg * 4 + 1) * 66 + bb] = bv.y;
            Bs[(kkg * 4 + 2) * 66 + bb] = bv.z;
            Bs[(kkg * 4 + 3) * 66 + bb] = bv.w;
        }
        __syncthreads();
#pragma unroll
        for (int k = 0; k < 16; k++) {
            float4 a0 = *(const float4*)&As[k * 132 + r0];
            float4 a1 = *(const float4*)&As[k * 132 + r0 + 4];
            ull b0 = *(const ull*)&Bs[k * 66 + c0];
            ull b1 = *(const ull*)&Bs[k * 66 + c0 + 2];
            ull sp;
            sp = splat2(a0.x); acc[0][0] = fma2(sp, b0, acc[0][0]); acc[0][1] = fma2(sp, b1, acc[0][1]);
            sp = splat2(a0.y); acc[1][0] = fma2(sp, b0, acc[1][0]); acc[1][1] = fma2(sp, b1, acc[1][1]);
            sp = splat2(a0.z); acc[2][0] = fma2(sp, b0, acc[2][0]); acc[2][1] = fma2(sp, b1, acc[2][1]);
            sp = splat2(a0.w); acc[3][0] = fma2(sp, b0, acc[3][0]); acc[3][1] = fma2(sp, b1, acc[3][1]);
            sp = splat2(a1.x); acc[4][0] = fma2(sp, b0, acc[4][0]); acc[4][1] = fma2(sp, b1, acc[4][1]);
            sp = splat2(a1.y); acc[5][0] = fma2(sp, b0, acc[5][0]); acc[5][1] = fma2(sp, b1, acc[5][1]);
            sp = splat2(a1.z); acc[6][0] = fma2(sp, b0, acc[6][0]); acc[6][1] = fma2(sp, b1, acc[6][1]);
            sp = splat2(a1.w); acc[7][0] = fma2(sp, b0, acc[7][0]); acc[7][1] = fma2(sp, b1, acc[7][1]);
        }
        __syncthreads();
    }
#pragma unroll
    for (int i = 0; i < 8; i++) {
        int row = bx * 128 + r0 + i;
        float bias = g_bias[row];
        float p0, p1, p2, p3;
        upk2(acc[i][0], p0, p1);
        upk2(acc[i][1], p2, p3);
        *(float4*)(g_xg + ((size_t)t * 2048 + row) * 64 + c0) =
            make_float4(p0 + bias, p1 + bias, p2 + bias, p3 + bias);
    }
}

// ---------------------------------------------------------------------------
// Phase 2: persistent recurrence, 128 CTAs x 256 threads, NO global barrier.
// CTA owns 4 hidden units -> 16 gate rows. Thread: 1 row x 4 cols.
// smem: Wt2 = pre-splatted {w,w} pairs [16 rows][520 k-pad] = 66.5KB
//       hsh = 2 x 16KB double-buffered h chunks, gsh = gate staging 4KB.
// Sync: per-CTA g_flags[c] = completed steps (release). Chunk j of the GEMM
// waits on flags of CTAs 16j..16j+15 only; polls pipelined 1 chunk ahead of
// the register prefetch. All 128 flags verified >= s before hout is written
// (overwrite of h_{s-1} is safe). Skew < 1 step => deadlock-free.
// ---------------------------------------------------------------------------
__global__ void __launch_bounds__(256, 1) k_rec(const float* __restrict__ Whh) {
    extern __shared__ __align__(16) char smraw[];
    ull*   Wt2 = (ull*)smraw;                          // 16*520 ull = 66560 B
    float* hsh = (float*)(smraw + 66560);              // 8192 fl    = 32768 B
    float* gsh = (float*)(smraw + 66560 + 32768);      // 1024 fl    =  4096 B

    const int tid  = threadIdx.x;
    const int h0   = blockIdx.x * 4;
    const int rloc = tid >> 4;                 // 0..15 local gate row
    const int c0   = (tid & 15) * 4;           // 4-col group
    const int grow = (rloc & 3) * 512 + h0 + (rloc >> 2);  // global gate row

    // fill pre-splatted W slab: Wt2[rl*520 + k] = {w,w}, w = Whh[grow(rl)][k]
#pragma unroll
    for (int j = 0; j < 8; j++) {
        int flat = tid + j * 256;              // float4 idx 0..2047
        int rl = flat >> 7, k4 = flat & 127;
        int grw = (rl & 3) * 512 + h0 + (rl >> 2);
        float4 w4 = *(const float4*)(Whh + (size_t)grw * 512 + k4 * 4);
        ull* wdst = Wt2 + rl * 520 + k4 * 4;
        wdst[0] = splat2(w4.x); wdst[1] = splat2(w4.y);
        wdst[2] = splat2(w4.z); wdst[3] = splat2(w4.w);
    }
    float cstate = 0.0f;                       // cell for (u2 = tid>>6, b = tid&63)
    __syncthreads();

    for (int s = 0; s < TSZ; s++) {
        const float* hin  = g_h + (s & 1) * 32768;
        float*       hout = g_h + ((s + 1) & 1) * 32768;
        const unsigned target = (unsigned)s;   // need h_s: producers done s steps

        // xg load first (overlaps the flag wait)
        float4 xg4 = __ldcs((const float4*)(g_xg + ((size_t)s * 2048 + grow) * 64 + c0));
        ull acc0 = pk2(xg4.x, xg4.y);
        ull acc1 = pk2(xg4.z, xg4.w);

        // wait for chunk 0 and 1 producers (flags 0..31)
        if (tid < 32) { poll_flag(g_flags + tid, target); fence_acq(); }
        __syncthreads();

        // stage chunk 0 (L2 loads: bypass L1, buffer was rewritten last step)
        {
            const float4* src = (const float4*)hin;
            float4* dst = (float4*)hsh;
            dst[tid]       = __ldcg(src + tid);
            dst[tid + 256] = __ldcg(src + tid + 256);
            dst[tid + 512] = __ldcg(src + tid + 512);
            dst[tid + 768] = __ldcg(src + tid + 768);
        }
        __syncthreads();

        for (int kc = 0; kc < 8; kc++) {
            float4 v0, v1, v2, v3;
            if (kc < 7) {   // prefetch next chunk (flags verified last chunk)
                const float4* src = (const float4*)(hin + (kc + 1) * 4096);
                v0 = __ldcg(src + tid);       v1 = __ldcg(src + tid + 256);
                v2 = __ldcg(src + tid + 512); v3 = __ldcg(src + tid + 768);
            }
            const ull*   wr = Wt2 + rloc * 520 + kc * 64;
            const float* hb = hsh + (kc & 1) * 4096;
#pragma unroll
            for (int k = 0; k < 64; k += 4) {
                ulonglong2 wa = *(const ulonglong2*)(wr + k);
                ulonglong2 wb = *(const ulonglong2*)(wr + k + 2);
                const float* hp = hb + k * 64 + c0;
                acc0 = fma2(wa.x, *(const ull*)(hp),       acc0);
                acc1 = fma2(wa.x, *(const ull*)(hp + 2),   acc1);
                acc0 = fma2(wa.y, *(const ull*)(hp + 64),  acc0);
                acc1 = fma2(wa.y, *(const ull*)(hp + 66),  acc1);
                acc0 = fma2(wb.x, *(const ull*)(hp + 128), acc0);
                acc1 = fma2(wb.x, *(const ull*)(hp + 130), acc1);
                acc0 = fma2(wb.y, *(const ull*)(hp + 192), acc0);
                acc1 = fma2(wb.y, *(const ull*)(hp + 194), acc1);
            }
            // pipeline the flag wait for chunk kc+2 (prefetched next iter)
            if (kc < 6 && tid < 16) {
                poll_flag(g_flags + (kc + 2) * 16 + tid, target);
                fence_acq();
            }
            if (kc < 7) {
                float4* dst = (float4*)(hsh + ((kc + 1) & 1) * 4096);
                dst[tid] = v0; dst[tid + 256] = v1;
                dst[tid + 512] = v2; dst[tid + 768] = v3;
            }
            __syncthreads();
        }

        // publish gate pre-activations
        {
            float p0, p1, p2, p3;
            upk2(acc0, p0, p1);
            upk2(acc1, p2, p3);
            *(float4*)&gsh[rloc * 64 + c0] = make_float4(p0, p1, p2, p3);
        }
        __syncthreads();

        // cell update: one cell per thread (u2 = tid>>6, b = tid&63)
        {
            int u2 = tid >> 6, b = tid & 63;
            float ig = fsig(gsh[(u2 * 4 + 0) * 64 + b]);
            float fg = fsig(gsh[(u2 * 4 + 1) * 64 + b]);
            float gg = ftanh(gsh[(u2 * 4 + 2) * 64 + b]);
            float og = fsig(gsh[(u2 * 4 + 3) * 64 + b]);
            cstate = fg * cstate + ig * gg;
            hout[(h0 + u2) * 64 + b] = og * ftanh(cstate);
        }
        __syncthreads();   // all hout STGs issued (CTA-wide order point)

        // release-publish our completed-step counter
        if (tid == 0) {
            asm volatile("fence.acq_rel.gpu;" ::: "memory");
            asm volatile("st.relaxed.gpu.global.u32 [%0],%1;"
                         :: "l"(g_flags + blockIdx.x), "r"(s + 1) : "memory");
        }
    }
}

// ---------------------------------------------------------------------------
// FC head: out[b][o] = sum_h h_last[h][b] * W_fc[o][h] + b_fc[o]
// warp-per-output, shfl reduction. (measured 6.8us)
// h_last lives in g_h buffer 0 (written at step 2047).
// ---------------------------------------------------------------------------
__global__ void __launch_bounds__(256) k_fc(const float* __restrict__ Wfc,
                                            const float* __restrict__ bfc,
                                            float* __restrict__ out) {
    int g    = blockIdx.x * 8 + (threadIdx.x >> 5);
    int lane = threadIdx.x & 31;
    int o = g >> 6, b = g & 63;
    float s = 0.0f;
#pragma unroll
    for (int j = 0; j < 16; j++) {
        int h = lane + j * 32;
        s += g_h[h * 64 + b] * Wfc[o * 512 + h];
    }
#pragma unroll
    for (int m = 16; m > 0; m >>= 1)
        s += __shfl_xor_sync(0xFFFFFFFFu, s, m);
    if (lane == 0) out[b * 10 + o] = s + bfc[o];
}

// ---------------------------------------------------------------------------
extern "C" void kernel_launch(void* const* d_in, const int* in_sizes, int n_in,
                              void* d_out, int out_size) {
    const float* x    = (const float*)d_in[0];
    const float* W_ih = (const float*)d_in[1];
    const float* W_hh = (const float*)d_in[2];
    const float* b_ih = (const float*)d_in[3];
    const float* b_hh = (const float*)d_in[4];
    const float* W_fc = (const float*)d_in[5];
    const float* b_fc = (const float*)d_in[6];
    float* out = (float*)d_out;

    const int SMEM_REC = 66560 + 32768 + 4096;   // 103424 B
    cudaFuncSetAttribute(k_rec, cudaFuncAttributeMaxDynamicSharedMemorySize, SMEM_REC);

    k_init<<<64, 256>>>(b_ih, b_hh);
    k_inproj<<<dim3(16, 2048), 256>>>(x, W_ih);
    k_rec<<<NCTA, 256, SMEM_REC>>>(W_hh);
    k_fc<<<80, 256>>>(W_fc, b_fc, out);
}

// round 11
// speedup vs baseline: 2.5493x; 2.1362x over previous
#include <cuda_runtime.h>
#include <cstdint>
#include <cstddef>
#include <math.h>

// ---------------------------------------------------------------------------
// LSTM  I=256 H=512 O=10 B=64 T=2048  (fp32, f32x2 packed-FMA pipe)
// R11: R10 with the h-staging bug fixed (32 float4/thread, full 128KB h
//      staged; R10 only staged 8 -> GEMM quarters 1-3 read garbage).
//   - warp tile 16r x 32c x 128k (4 k-quarters x 2 col-halves): ~3 LDS
//     wavefronts/warp/k -> LDS under the 4096-cyc FMA2 floor
//   - whole h resident in smem each step (208KB total, 1 CTA/SM)
//   - k-partials reduced via smem; xg folded in at the cell update
//   - single-counter barrier: red.relaxed.gpu publish + 1 relaxed poller
// ---------------------------------------------------------------------------

#define TSZ  2048
#define NCTA 128

typedef unsigned long long ull;

// scratch (__device__ globals are the sanctioned scratch mechanism)
__device__ float    g_xg[268435456];     // 1 GiB: [T][4H][B]  (2048*2048*64)
__device__ float    g_h[2 * 512 * 64];   // double-buffered h: [H][B]
__device__ float    g_bias[2048];        // b_ih + b_hh
__device__ unsigned g_count;             // chip-barrier monotonic counter

// ---- packed f32x2 helpers (Blackwell dual-fp32 pipe) ----------------------
__device__ __forceinline__ ull splat2(float a) {
    ull r; asm("mov.b64 %0,{%1,%1};" : "=l"(r) : "f"(a)); return r;
}
__device__ __forceinline__ ull fma2(ull a, ull b, ull c) {
    ull d; asm("fma.rn.f32x2 %0,%1,%2,%3;" : "=l"(d) : "l"(a), "l"(b), "l"(c));
    return d;
}
__device__ __forceinline__ void upk2(ull v, float& a, float& b) {
    asm("mov.b64 {%0,%1},%2;" : "=f"(a), "=f"(b) : "l"(v));
}

// fast activations (rel err ~1e-6; budget 1e-3)
__device__ __forceinline__ float fsig(float x) {
    return __fdividef(1.0f, 1.0f + __expf(-x));
}
__device__ __forceinline__ float ftanh(float x) {
    return 1.0f - __fdividef(2.0f, __expf(2.0f * x) + 1.0f);
}

// ---------------------------------------------------------------------------
__global__ void k_init(const float* __restrict__ bih, const float* __restrict__ bhh) {
    int tid = blockIdx.x * blockDim.x + threadIdx.x;
    int nt  = gridDim.x * blockDim.x;
    if (tid < 2048) g_bias[tid] = bih[tid] + bhh[tid];
    for (int i = tid; i < 2 * 512 * 64; i += nt) g_h[i] = 0.0f;
    if (tid == 0) g_count = 0u;
}

// ---------------------------------------------------------------------------
// Phase 1: xg[t][row][b] = sum_i W_ih[row][i] * x[b][t][i] + bias[row]
// (unchanged -- passing since R5)
// ---------------------------------------------------------------------------
__global__ void __launch_bounds__(256) k_inproj(const float* __restrict__ x,
                                                const float* __restrict__ Wih) {
    __shared__ __align__(16) float As[16 * 132];
    __shared__ __align__(16) float Bs[16 * 66];

    const int tid = threadIdx.x;
    const int bx  = blockIdx.x;
    const int t   = blockIdx.y;
    const int tr  = tid >> 4, tc = tid & 15;
    const int r0  = tr * 8,  c0 = tc * 4;
    const int kkg = tid & 3;
    const int bb  = tid >> 2;

    ull acc[8][2];
#pragma unroll
    for (int i = 0; i < 8; i++) { acc[i][0] = 0ull; acc[i][1] = 0ull; }

    for (int k0 = 0; k0 < 256; k0 += 16) {
#pragma unroll
        for (int j = 0; j < 2; j++) {
            int rr = (tid >> 2) + j * 64;
            float4 av = *(const float4*)(Wih + (size_t)(bx * 128 + rr) * 256 + k0 + kkg * 4);
            As[(kkg * 4 + 0) * 132 + rr] = av.x;
            As[(kkg * 4 + 1) * 132 + rr] = av.y;
            As[(kkg * 4 + 2) * 132 + rr] = av.z;
            As[(kkg * 4 + 3) * 132 + rr] = av.w;
        }
        {
            float4 bv = *(const float4*)(x + ((size_t)bb * 2048 + t) * 256 + k0 + kkg * 4);
            Bs[(kkg * 4 + 0) * 66 + bb] = bv.x;
            Bs[(kkg * 4 + 1) * 66 + bb] = bv.y;
            Bs[(kkg * 4 + 2) * 66 + bb] = bv.z;
            Bs[(kkg * 4 + 3) * 66 + bb] = bv.w;
        }
        __syncthreads();
#pragma unroll
        for (int k = 0; k < 16; k++) {
            float4 a0 = *(const float4*)&As[k * 132 + r0];
            float4 a1 = *(const float4*)&As[k * 132 + r0 + 4];
            ull b0 = *(const ull*)&Bs[k * 66 + c0];
            ull b1 = *(const ull*)&Bs[k * 66 + c0 + 2];
            ull sp;
            sp = splat2(a0.x); acc[0][0] = fma2(sp, b0, acc[0][0]); acc[0][1] = fma2(sp, b1, acc[0][1]);
            sp = splat2(a0.y); acc[1][0] = fma2(sp, b0, acc[1][0]); acc[1][1] = fma2(sp, b1, acc[1][1]);
            sp = splat2(a0.z); acc[2][0] = fma2(sp, b0, acc[2][0]); acc[2][1] = fma2(sp, b1, acc[2][1]);
            sp = splat2(a0.w); acc[3][0] = fma2(sp, b0, acc[3][0]); acc[3][1] = fma2(sp, b1, acc[3][1]);
            sp = splat2(a1.x); acc[4][0] = fma2(sp, b0, acc[4][0]); acc[4][1] = fma2(sp, b1, acc[4][1]);
            sp = splat2(a1.y); acc[5][0] = fma2(sp, b0, acc[5][0]); acc[5][1] = fma2(sp, b1, acc[5][1]);
            sp = splat2(a1.z); acc[6][0] = fma2(sp, b0, acc[6][0]); acc[6][1] = fma2(sp, b1, acc[6][1]);
            sp = splat2(a1.w); acc[7][0] = fma2(sp, b0, acc[7][0]); acc[7][1] = fma2(sp, b1, acc[7][1]);
        }
        __syncthreads();
    }
#pragma unroll
    for (int i = 0; i < 8; i++) {
        int row = bx * 128 + r0 + i;
        float bias = g_bias[row];
        float p0, p1, p2, p3;
        upk2(acc[i][0], p0, p1);
        upk2(acc[i][1], p2, p3);
        *(float4*)(g_xg + ((size_t)t * 2048 + row) * 64 + c0) =
            make_float4(p0 + bias, p1 + bias, p2 + bias, p3 + bias);
    }
}

// ---------------------------------------------------------------------------
// Phase 2: persistent recurrence, 128 CTAs x 256 threads, 1 CTA/SM.
// CTA owns 4 hidden units -> 16 gate rows (rl = unit*4 + gate).
// smem: Wt2 = pre-splatted {w,w} ull [512 k][16 rows]        = 64 KB
//       hs  = full h [512 k][64 b]                           = 128 KB
//       gp  = k-quarter partials [4][16][64]                 = 16 KB
// Warp (q = wid&3 k-quarter, ch = wid>>2 col-half): 16r x 32c x 128k.
// Lane (rg = lane>>3, cg = lane&7): 4 rows x 4 cols.
// ---------------------------------------------------------------------------
__global__ void __launch_bounds__(256, 1) k_rec(const float* __restrict__ Whh) {
    extern __shared__ __align__(16) char smraw[];
    ull*   Wt2 = (ull*)smraw;                          // 512*16 ull = 65536 B
    float* hs  = (float*)(smraw + 65536);              // 512*64 fl  = 131072 B
    float* gp  = (float*)(smraw + 65536 + 131072);     // 4*16*64 fl = 16384 B

    const int tid  = threadIdx.x;
    const int h0   = blockIdx.x * 4;
    const int wid  = tid >> 5, lane = tid & 31;
    const int q    = wid & 3;                 // k-quarter
    const int ch   = wid >> 2;                // col half
    const int rg   = lane >> 3, cg = lane & 7;
    const int r0   = rg * 4;                  // 4 rows
    const int c0   = ch * 32 + cg * 4;        // 4 cols
    const int u2   = tid >> 6, b = tid & 63;  // cell-update mapping

    // fill pre-splatted W slab: Wt2[k*16 + rl] = {w,w},
    // w = Whh[(rl&3)*512 + h0 + (rl>>2)][k]
#pragma unroll
    for (int j = 0; j < 8; j++) {
        int flat = tid + j * 256;              // float4 idx 0..2047
        int rl = flat >> 7, k4 = flat & 127;
        int grw = (rl & 3) * 512 + h0 + (rl >> 2);
        float4 w4 = *(const float4*)(Whh + (size_t)grw * 512 + k4 * 4);
        Wt2[(k4 * 4 + 0) * 16 + rl] = splat2(w4.x);
        Wt2[(k4 * 4 + 1) * 16 + rl] = splat2(w4.y);
        Wt2[(k4 * 4 + 2) * 16 + rl] = splat2(w4.z);
        Wt2[(k4 * 4 + 3) * 16 + rl] = splat2(w4.w);
    }
    float cstate = 0.0f;
    __syncthreads();

    for (int s = 0; s < TSZ; s++) {
        const float* hin  = g_h + (s & 1) * 32768;
        float*       hout = g_h + ((s + 1) & 1) * 32768;

        // ---- wait: all CTAs completed step s-1 --------------------------
        if (tid == 0) {
            const unsigned target = (unsigned)s * NCTA;
            unsigned v;
            do {
                asm volatile("ld.relaxed.gpu.global.u32 %0,[%1];"
                             : "=r"(v) : "l"(&g_count));
            } while (v < target);
            asm volatile("fence.acq_rel.gpu;" ::: "memory");
        }
        __syncthreads();

        // xg for this thread's cell (prefetch; overlaps staging latency)
        float xgi = __ldcs(g_xg + ((size_t)s * 2048 + 0 * 512 + h0 + u2) * 64 + b);
        float xgf = __ldcs(g_xg + ((size_t)s * 2048 + 1 * 512 + h0 + u2) * 64 + b);
        float xgg = __ldcs(g_xg + ((size_t)s * 2048 + 2 * 512 + h0 + u2) * 64 + b);
        float xgo = __ldcs(g_xg + ((size_t)s * 2048 + 3 * 512 + h0 + u2) * 64 + b);

        // ---- stage FULL h into smem: 8192 float4, 32 per thread ---------
        // (R10 bug: only 8/thread were staged -> 3/4 of hs was garbage)
        {
            const float4* src = (const float4*)hin;
            float4*       dst = (float4*)hs;
#pragma unroll
            for (int j = 0; j < 4; j++) {
                float4 t0 = __ldcg(src + tid + (j * 8 + 0) * 256);
                float4 t1 = __ldcg(src + tid + (j * 8 + 1) * 256);
                float4 t2 = __ldcg(src + tid + (j * 8 + 2) * 256);
                float4 t3 = __ldcg(src + tid + (j * 8 + 3) * 256);
                float4 t4 = __ldcg(src + tid + (j * 8 + 4) * 256);
                float4 t5 = __ldcg(src + tid + (j * 8 + 5) * 256);
                float4 t6 = __ldcg(src + tid + (j * 8 + 6) * 256);
                float4 t7 = __ldcg(src + tid + (j * 8 + 7) * 256);
                dst[tid + (j * 8 + 0) * 256] = t0;
                dst[tid + (j * 8 + 1) * 256] = t1;
                dst[tid + (j * 8 + 2) * 256] = t2;
                dst[tid + (j * 8 + 3) * 256] = t3;
                dst[tid + (j * 8 + 4) * 256] = t4;
                dst[tid + (j * 8 + 5) * 256] = t5;
                dst[tid + (j * 8 + 6) * 256] = t6;
                dst[tid + (j * 8 + 7) * 256] = t7;
            }
        }
        __syncthreads();

        // ---- GEMM: this warp's 128-k quarter ----------------------------
        ull a00 = 0, a01 = 0, a10 = 0, a11 = 0;
        ull a20 = 0, a21 = 0, a30 = 0, a31 = 0;
        {
            const int kbeg = q * 128;
#pragma unroll 8
            for (int k = kbeg; k < kbeg + 128; k++) {
                ulonglong2 wa = *(const ulonglong2*)(Wt2 + k * 16 + r0);     // rows r0,r0+1
                ulonglong2 wb = *(const ulonglong2*)(Wt2 + k * 16 + r0 + 2); // rows r0+2,+3
                ulonglong2 hv = *(const ulonglong2*)(hs + k * 64 + c0);      // cols c0..+3
                a00 = fma2(wa.x, hv.x, a00); a01 = fma2(wa.x, hv.y, a01);
                a10 = fma2(wa.y, hv.x, a10); a11 = fma2(wa.y, hv.y, a11);
                a20 = fma2(wb.x, hv.x, a20); a21 = fma2(wb.x, hv.y, a21);
                a30 = fma2(wb.y, hv.x, a30); a31 = fma2(wb.y, hv.y, a31);
            }
        }
        // write k-quarter partials
        {
            float* gq = gp + (q * 16) * 64;
            *(ulonglong2*)(gq + (r0 + 0) * 64 + c0) = make_ulonglong2(a00, a01);
            *(ulonglong2*)(gq + (r0 + 1) * 64 + c0) = make_ulonglong2(a10, a11);
            *(ulonglong2*)(gq + (r0 + 2) * 64 + c0) = make_ulonglong2(a20, a21);
            *(ulonglong2*)(gq + (r0 + 3) * 64 + c0) = make_ulonglong2(a30, a31);
        }
        __syncthreads();

        // ---- reduce partials + cell update (one cell per thread) --------
        {
            int rI = u2 * 4 + 0, rF = u2 * 4 + 1, rG = u2 * 4 + 2, rO = u2 * 4 + 3;
            float gi = xgi, gf = xgf, gg = xgg, go = xgo;
#pragma unroll
            for (int qq = 0; qq < 4; qq++) {
                const float* gq = gp + (qq * 16) * 64;
                gi += gq[rI * 64 + b];
                gf += gq[rF * 64 + b];
                gg += gq[rG * 64 + b];
                go += gq[rO * 64 + b];
            }
            float ig = fsig(gi), fg = fsig(gf), gt = ftanh(gg), og = fsig(go);
            cstate = fg * cstate + ig * gt;
            float hv = og * ftanh(cstate);
            asm volatile("st.global.cg.f32 [%0], %1;"
                         :: "l"(hout + (h0 + u2) * 64 + b), "f"(hv) : "memory");
        }
        __syncthreads();   // all hout stores issued (CTA order point)

        // ---- publish: bump global counter (no-return reduction) ---------
        if (tid == 0) {
            asm volatile("fence.acq_rel.gpu;" ::: "memory");
            asm volatile("red.relaxed.gpu.global.add.u32 [%0], %1;"
                         :: "l"(&g_count), "r"(1u) : "memory");
        }
    }
}

// ---------------------------------------------------------------------------
// FC head: out[b][o] = sum_h h_last[h][b] * W_fc[o][h] + b_fc[o]
// warp-per-output, shfl reduction. h_last = g_h buffer 0.
// ---------------------------------------------------------------------------
__global__ void __launch_bounds__(256) k_fc(const float* __restrict__ Wfc,
                                            const float* __restrict__ bfc,
                                            float* __restrict__ out) {
    int g    = blockIdx.x * 8 + (threadIdx.x >> 5);
    int lane = threadIdx.x & 31;
    int o = g >> 6, b = g & 63;
    float s = 0.0f;
#pragma unroll
    for (int j = 0; j < 16; j++) {
        int h = lane + j * 32;
        s += g_h[h * 64 + b] * Wfc[o * 512 + h];
    }
#pragma unroll
    for (int m = 16; m > 0; m >>= 1)
        s += __shfl_xor_sync(0xFFFFFFFFu, s, m);
    if (lane == 0) out[b * 10 + o] = s + bfc[o];
}

// ---------------------------------------------------------------------------
extern "C" void kernel_launch(void* const* d_in, const int* in_sizes, int n_in,
                              void* d_out, int out_size) {
    const float* x    = (const float*)d_in[0];
    const float* W_ih = (const float*)d_in[1];
    const float* W_hh = (const float*)d_in[2];
    const float* b_ih = (const float*)d_in[3];
    const float* b_hh = (const float*)d_in[4];
    const float* W_fc = (const float*)d_in[5];
    const float* b_fc = (const float*)d_in[6];
    float* out = (float*)d_out;

    const int SMEM_REC = 65536 + 131072 + 16384;   // 212992 B (<227KB cap)
    cudaFuncSetAttribute(k_rec, cudaFuncAttributeMaxDynamicSharedMemorySize, SMEM_REC);

    k_init<<<64, 256>>>(b_ih, b_hh);
    k_inproj<<<dim3(16, 2048), 256>>>(x, W_ih);
    k_rec<<<NCTA, 256, SMEM_REC>>>(W_hh);
    k_fc<<<80, 256>>>(W_fc, b_fc, out);
}